// round 17
// baseline (speedup 1.0000x reference)
#include <cuda_runtime.h>

// RoIAlign2D: features (4,256,96,96) f32, rois (1024,5) f32 -> out (1024,256,7,7) f32
// OUT_SIZE=7, SPATIAL_SCALE=0.0625, SAMPLE_NUM=2
//
// v8: two kernels.
//  1) transpose_feat: features -> channel-last g_feat_t[b][y][x][c] (static
//     __device__ scratch). 32x33 smem tile transpose, coalesced both sides.
//  2) roi_align_v8: v5b structure (y-half blocks, geometry tables, GROUP=32,
//     lane=channel) but staging reads channel-last: one patch cell for 32
//     channels = exactly one 128B line (1 LDG wf, 1 STS wf). Patch layout
//     [y][x][c] with cell stride 32 -> every smem access is 32 consecutive
//     words (conflict-free), no odd-stride tricks needed.

#define CC     256
#define HH     96
#define WW     96
#define HW     (HH * WW)        // 9216
#define SCALE  0.0625f
#define SW     21               // patch x extent
#define PY     12               // max y span per half
#define YSTRIDE (SW * 32)       // 672 words per patch row
#define GROUP  32
#define NOUTMX 28
#define CPADO  33

#define PATCH_ELEMS  (PY * YSTRIDE)             // 8064
#define OUTBUF_ELEMS (NOUTMX * CPADO)           // 924
#define TAB_FLOATS   (22 * 4)
#define SMEM_BYTES   ((TAB_FLOATS + PATCH_ELEMS + OUTBUF_ELEMS) * 4)  // 36304

__device__ __align__(128) float g_feat_t[4 * HW * CC];   // 37.75 MB scratch

// ---------------- pre-pass: [b][c][p] -> [b][p][c] ----------------
__global__ __launch_bounds__(256) void transpose_feat(const float* __restrict__ feat)
{
    __shared__ float tile[32][33];
    int tx = threadIdx.x, ty = threadIdx.y;
    int ptile = blockIdx.x, ctile = blockIdx.y, b = blockIdx.z;

    int p = ptile * 32 + tx;
    #pragma unroll
    for (int i = 0; i < 4; ++i) {
        int c = ctile * 32 + ty + i * 8;
        tile[ty + i * 8][tx] = feat[(size_t)(b * CC + c) * HW + p];
    }
    __syncthreads();
    int c2 = ctile * 32 + tx;
    #pragma unroll
    for (int i = 0; i < 4; ++i) {
        int p2 = ptile * 32 + ty + i * 8;
        g_feat_t[(size_t)(b * HW + p2) * CC + c2] = tile[tx][ty + i * 8];
    }
}

// ---------------- main kernel ----------------
__global__ __launch_bounds__(256) void roi_align_v8(
    const float* __restrict__ rois,
    float* __restrict__ out)
{
    extern __shared__ float smem[];
    float4* ytab   = (float4*)smem;             // [8]
    float4* xtab   = (float4*)smem + 8;         // [14]
    float*  patch  = smem + TAB_FLOATS;         // [PY][SW][32]
    float*  outbuf = patch + PATCH_ELEMS;       // [NOUTMX][CPADO]

    int blk = blockIdx.x;
    int k   = blk >> 4;                 // roi
    int g   = (blk >> 1) & 7;           // channel group
    int h   = blk & 1;                  // y-half
    int c0  = g * GROUP;

    int phbase = h ? 4 : 0;
    int nrows  = h ? 3 : 4;
    int nout   = nrows * 7;             // 21 or 28
    int s0     = h ? 8 : 0;
    int ny     = 2 * nrows;

    const float* r = rois + k * 5;
    int   b  = (int)__ldg(r);
    float x1 = __ldg(r + 1) * SCALE;
    float y1 = __ldg(r + 2) * SCALE;
    float x2 = __ldg(r + 3) * SCALE;
    float y2 = __ldg(r + 4) * SCALE;

    float bw = fmaxf(x2 - x1, 1.0f) * (1.0f / 7.0f);
    float bh = fmaxf(y2 - y1, 1.0f) * (1.0f / 7.0f);

    // Patch bounds: monotone clipped coords -> first/last sample bound all taps,
    // clipping keeps everything in-bounds.
    float xcf = fminf(fmaxf(x1 + bw * 0.25f, 0.0f), (float)(WW - 1));
    int   xs0 = (int)floorf(xcf);
    float xce = fminf(fmaxf(x1 + bw * 6.75f, 0.0f), (float)(WW - 1));
    int xspan = min((int)floorf(xce) + 1, WW - 1) - xs0 + 1;         // <= 21

    float yoff0 = 0.25f + 0.5f * (float)s0;
    float yoffE = 0.25f + 0.5f * (float)(s0 + ny - 1);
    float ycf = fminf(fmaxf(y1 + bh * yoff0, 0.0f), (float)(HH - 1));
    int   ys0 = (int)floorf(ycf);
    float yce = fminf(fmaxf(y1 + bh * yoffE, 0.0f), (float)(HH - 1));
    int yspan = min((int)floorf(yce) + 1, HH - 1) - ys0 + 1;         // <= 12

    int tid  = threadIdx.x;
    int w    = tid >> 5;
    int lane = tid & 31;

    // ---- geometry tables (offsets premultiplied to patch-word units) ----
    if (tid < 22 && (tid < ny || tid >= 8)) {
        bool  isY = tid < 8;
        int   s   = isY ? (s0 + tid) : (tid - 8);
        float start = isY ? y1 : x1;
        float bsz   = isY ? bh : bw;
        int   size  = isY ? HH : WW;
        int   org   = isY ? ys0 : xs0;
        int   mul   = isY ? YSTRIDE : 32;

        float c  = start + bsz * (0.25f + 0.5f * (float)s);
        bool  v  = (c >= -1.0f) && (c <= (float)size);
        float cc = fminf(fmaxf(c, 0.0f), (float)(size - 1));
        float fl = floorf(cc);
        int   lo = (int)fl;
        int   hi = min(lo + 1, size - 1);
        float fr = cc - fl;
        float4 e;
        e.x = __int_as_float((lo - org) * mul);
        e.y = __int_as_float((hi - org) * mul);
        e.z = v ? (1.0f - fr) : 0.0f;
        e.w = v ? fr : 0.0f;
        if (isY) ytab[tid] = e; else xtab[tid - 8] = e;
    }

    // ---- stage patch from channel-last features ----
    // One cell = 32 consecutive floats = 1 LDG wf + 1 STS wf. Warps split x.
    const float* fT = g_feat_t + (size_t)b * (HW * CC) + c0 + lane;
    for (int y = 0; y < yspan; ++y) {
        const float* grow = fT + ((ys0 + y) * WW + xs0) * CC;
        float*       prow = patch + y * YSTRIDE + lane;
        for (int x = w; x < xspan; x += 8)
            prow[x * 32] = __ldg(grow + x * CC);
    }
    __syncthreads();

    // ---- compute: warp per output, lane = channel ----
    const float* plane = patch + lane;
    for (int o = w; o < nout; o += 8) {
        int ly = o / 7;
        int pw = o - ly * 7;
        float4 ya = ytab[2 * ly], yb = ytab[2 * ly + 1];
        float4 xa = xtab[2 * pw], xb = xtab[2 * pw + 1];
        float acc = 0.0f;
        #pragma unroll
        for (int sy = 0; sy < 2; ++sy) {
            float4 ye = sy ? yb : ya;
            int rl = __float_as_int(ye.x);
            int rh = __float_as_int(ye.y);
            #pragma unroll
            for (int sx = 0; sx < 2; ++sx) {
                float4 xe = sx ? xb : xa;
                int cl = __float_as_int(xe.x);
                int ch = __float_as_int(xe.y);
                float tll = plane[rl + cl];
                float tlh = plane[rl + ch];
                float thl = plane[rh + cl];
                float thh = plane[rh + ch];
                float tlo = xe.z * tll + xe.w * tlh;
                float thi = xe.z * thl + xe.w * thh;
                acc += ye.z * tlo + ye.w * thi;
            }
        }
        outbuf[o * CPADO + lane] = acc * 0.25f;
    }
    __syncthreads();

    // ---- coalesced writeback (stride-33 LDS: conflict-free) ----
    float* obase = out + ((size_t)k * CC + c0) * 49 + phbase * 7;
    for (int e = tid; e < GROUP * NOUTMX; e += 256) {
        int c = e / NOUTMX;
        int o = e - c * NOUTMX;
        if (o < nout)
            obase[c * 49 + o] = outbuf[o * CPADO + c];
    }
}

extern "C" void kernel_launch(void* const* d_in, const int* in_sizes, int n_in,
                              void* d_out, int out_size)
{
    const float* feat = (const float*)d_in[0];
    const float* rois = (const float*)d_in[1];
    float*       out  = (float*)d_out;

    cudaFuncSetAttribute(roi_align_v8,
                         cudaFuncAttributeMaxDynamicSharedMemorySize, SMEM_BYTES);

    dim3 tb(32, 8);
    dim3 tg(HW / 32, CC / 32, 4);           // (288, 8, 4)
    transpose_feat<<<tg, tb>>>(feat);

    int n_rois = in_sizes[1] / 5;           // 1024
    roi_align_v8<<<n_rois * 16, 256, SMEM_BYTES>>>(rois, out);
}